// round 2
// baseline (speedup 1.0000x reference)
#include <cuda_runtime.h>
#include <stdint.h>

// Problem shape (fixed by the reference)
#define B_DIM   64
#define F_DIM   80
#define T_DIM   640
#define FT      (F_DIM * T_DIM)          // 51200
#define S_TOT   (B_DIM * FT)             // 3,276,800
#define N_AUX   32
#define NB      (N_AUX * B_DIM)          // 2048
#define MASK_WORDS (S_TOT / 32)          // 102400
#define THRESH  20.0f
#define BIG_F   3.0e38f                  // sentinel "no neighbor" => comparison false

// Scratch: strain peak bitmask (400 KB, L2-resident across the aux pass) +
// per-batch strain peak counts. __device__ globals per allocation rules.
__device__ uint32_t g_mask[MASK_WORDS];
__device__ int      g_c1[B_DIM];

// ---------------------------------------------------------------------------
// Kernel 1: strain peak mask + per-batch count c1[b].
// One block per batch b (64 blocks x 256 threads), float4 per thread per iter.
// Peak detection is on the WHOLE flattened [B,F,T] array (neighbors cross row
// and batch boundaries, matching the reference's reshape(-1) semantics).
// Threshold > 0 makes the reference's clip(.,0) algebraically redundant.
// ---------------------------------------------------------------------------
__global__ __launch_bounds__(256)
void strain_mask_kernel(const float* __restrict__ x) {
    const int b    = blockIdx.x;
    const int base = b * FT;
    int cnt = 0;

    #pragma unroll 4
    for (int it = 0; it < FT / (256 * 4); ++it) {        // 50 iterations
        const int j = base + (it * 256 + threadIdx.x) * 4;
        const float4 v = *reinterpret_cast<const float4*>(x + j);
        const float left  = (j > 0)         ? x[j - 1] : BIG_F;
        const float right = (j + 4 < S_TOT) ? x[j + 4] : BIG_F;

        const bool pk0 = (v.x >= THRESH) & (v.x > left) & (v.x > v.y);
        const bool pk1 = (v.y >= THRESH) & (v.y > v.x)  & (v.y > v.z);
        const bool pk2 = (v.z >= THRESH) & (v.z > v.y)  & (v.z > v.w);
        const bool pk3 = (v.w >= THRESH) & (v.w > v.z)  & (v.w > right);

        // 4 bits per thread, 128 bits per warp -> each warp owns 4 mask words.
        const unsigned nib = (unsigned)pk0 | ((unsigned)pk1 << 1)
                           | ((unsigned)pk2 << 2) | ((unsigned)pk3 << 3);
        // gather nibbles: lane L holds bits [4L, 4L+4) of a 128-bit span.
        // Use 4 ballots, one per mask word (lanes 0-7 -> word0, etc).
        const unsigned full = __ballot_sync(0xffffffffu, true); (void)full;
        // pack: word w collects nibbles from lanes [8w, 8w+8)
        #pragma unroll
        for (int w = 0; w < 4; ++w) {
            // each lane contributes (nib << (4*(lane&7))) if lane in group w
            const int lane = threadIdx.x & 31;
            unsigned contrib = (lane >> 3 == w) ? (nib << ((lane & 7) * 4)) : 0u;
            // warp-reduce OR
            #pragma unroll
            for (int off = 16; off > 0; off >>= 1)
                contrib |= __shfl_down_sync(0xffffffffu, contrib, off);
            if (lane == 0) {
                const int word0 = (j >> 5);  // lane0's j is 128-aligned in elements
                g_mask[word0 + w] = contrib;
            }
        }
        cnt += (int)pk0 + (int)pk1 + (int)pk2 + (int)pk3;
    }

    // block reduce cnt
    __shared__ int sred[8];
    #pragma unroll
    for (int off = 16; off > 0; off >>= 1)
        cnt += __shfl_down_sync(0xffffffffu, cnt, off);
    const int warp = threadIdx.x >> 5;
    if ((threadIdx.x & 31) == 0) sred[warp] = cnt;
    __syncthreads();
    if (threadIdx.x == 0) {
        int v = 0;
        #pragma unroll
        for (int w = 0; w < 8; ++w) v += sred[w];
        g_c1[b] = v;
    }
}

// ---------------------------------------------------------------------------
// Kernel 2: per-(aux n, batch b) slice. Aux peaks computed on the fly, ANDed
// with the strain bitmask (L2-resident), intersection + aux-count accumulated
// packed in one u32 (each field <= 51200 < 2^16), then jac/ratio emitted.
// 2048 blocks x 256 threads, float4 per thread per iter, 50 iters.
// ---------------------------------------------------------------------------
__global__ __launch_bounds__(256)
void aux_iou_kernel(const float* __restrict__ aux, float* __restrict__ out) {
    const int blk = blockIdx.x;          // 0..2047
    const int n   = blk >> 6;            // aux channel
    const int b   = blk & 63;            // batch
    const float* __restrict__ p = aux + (size_t)n * S_TOT;
    const int base = b * FT;

    unsigned packed = 0;                 // bits[0:16)=inter, bits[16:32)=c2

    int j = base + threadIdx.x * 4;
    #pragma unroll 4
    for (int it = 0; it < FT / (256 * 4); ++it, j += 256 * 4) {   // 50 iterations
        const float4 v = *reinterpret_cast<const float4*>(p + j);
        const float left  = (j > 0)         ? p[j - 1] : BIG_F;
        const float right = (j + 4 < S_TOT) ? p[j + 4] : BIG_F;

        const unsigned pk0 = (v.x >= THRESH) & (v.x > left) & (v.x > v.y);
        const unsigned pk1 = (v.y >= THRESH) & (v.y > v.x)  & (v.y > v.z);
        const unsigned pk2 = (v.z >= THRESH) & (v.z > v.y)  & (v.z > v.w);
        const unsigned pk3 = (v.w >= THRESH) & (v.w > v.z)  & (v.w > right);

        const unsigned mb = g_mask[j >> 5] >> (j & 31);  // 4 consecutive bits
        const unsigned inter = (pk0 & (mb & 1u))
                             + (pk1 & ((mb >> 1) & 1u))
                             + (pk2 & ((mb >> 2) & 1u))
                             + (pk3 & ((mb >> 3) & 1u));
        const unsigned c2 = pk0 + pk1 + pk2 + pk3;
        packed += inter | (c2 << 16);
    }

    // block reduce the packed counter
    __shared__ unsigned sred[8];
    #pragma unroll
    for (int off = 16; off > 0; off >>= 1)
        packed += __shfl_down_sync(0xffffffffu, packed, off);
    const int warp = threadIdx.x >> 5;
    if ((threadIdx.x & 31) == 0) sred[warp] = packed;
    __syncthreads();
    if (threadIdx.x == 0) {
        unsigned tot = 0;
        #pragma unroll
        for (int w = 0; w < 8; ++w) tot += sred[w];
        const int inter = (int)(tot & 0xffffu);
        const int c2    = (int)(tot >> 16);
        const int c1    = g_c1[b];

        const float fi  = (float)inter;
        const float fc1 = (float)c1;
        const float uni = fc1 + (float)c2 - fi;

        float jac, ratio;
        if (inter == 0 && uni == 0.0f) {          // empty & empty -> 1.0 (ref)
            jac = 1.0f; ratio = 1.0f;
        } else {
            jac   = fi / uni;                     // uni > 0 here
            ratio = (c1 > 0) ? (fi / fc1) : 0.0f; // 0/0 -> nan_to_num -> 0
        }
        const int o = n * B_DIM + b;
        out[o]      = jac;                        // iou, flat [N_aux*B]
        out[NB + o] = ratio;                      // corr, flat [N_aux*B]
    }
}

extern "C" void kernel_launch(void* const* d_in, const int* in_sizes, int n_in,
                              void* d_out, int out_size) {
    const float* strain = (const float*)d_in[0];   // [64, 80, 640] fp32
    const float* aux    = (const float*)d_in[1];   // [32, 64, 80, 640] fp32
    float* out = (float*)d_out;                    // [4096] = iou(2048) ++ corr(2048)

    strain_mask_kernel<<<B_DIM, 256>>>(strain);
    aux_iou_kernel<<<NB, 256>>>(aux, out);
}

// round 3
// speedup vs baseline: 1.4108x; 1.4108x over previous
#include <cuda_runtime.h>
#include <stdint.h>

// Problem shape (fixed by the reference)
#define B_DIM   64
#define F_DIM   80
#define T_DIM   640
#define FT      (F_DIM * T_DIM)          // 51200
#define S_TOT   (B_DIM * FT)             // 3,276,800
#define N_AUX   32
#define NB      (N_AUX * B_DIM)          // 2048
#define MASK_WORDS (S_TOT / 32)          // 102400
#define THRESH  20.0f
#define BIG_F   3.0e38f                  // sentinel "no neighbor" => comparison false
#define FULL    0xffffffffu

// Scratch: strain peak bitmask (400 KB, L2-resident across the aux pass).
__device__ uint32_t g_mask[MASK_WORDS];

// ---------------------------------------------------------------------------
// Kernel 1: strain peak bitmask. 3200 blocks x 256 threads, one float4 each.
// Neighbors via warp shuffles (+ per-warp-edge predicated scalar load).
// Nibble->word packing via 3-step shfl_xor OR butterfly over 8-lane groups.
// Peak detection runs on the WHOLE flattened [B,F,T] array, matching the
// reference's reshape(-1); threshold > 0 makes clip(.,0) redundant.
// ---------------------------------------------------------------------------
__global__ __launch_bounds__(256)
void strain_mask_kernel(const float* __restrict__ x) {
    const int lane = threadIdx.x & 31;
    const int j = (blockIdx.x * 256 + threadIdx.x) * 4;

    const float4 v = *reinterpret_cast<const float4*>(x + j);

    float left = __shfl_up_sync(FULL, v.w, 1);
    if (lane == 0)  left  = (j > 0) ? x[j - 1] : BIG_F;
    float right = __shfl_down_sync(FULL, v.x, 1);
    if (lane == 31) right = (j + 4 < S_TOT) ? x[j + 4] : BIG_F;

    const unsigned pk0 = (v.x >= THRESH) & (v.x > left) & (v.x > v.y);
    const unsigned pk1 = (v.y >= THRESH) & (v.y > v.x)  & (v.y > v.z);
    const unsigned pk2 = (v.z >= THRESH) & (v.z > v.y)  & (v.z > v.w);
    const unsigned pk3 = (v.w >= THRESH) & (v.w > v.z)  & (v.w > right);

    unsigned val = (pk0 | (pk1 << 1) | (pk2 << 2) | (pk3 << 3)) << ((lane & 7) * 4);
    val |= __shfl_xor_sync(FULL, val, 1);
    val |= __shfl_xor_sync(FULL, val, 2);
    val |= __shfl_xor_sync(FULL, val, 4);
    if ((lane & 7) == 0) g_mask[j >> 5] = val;
}

// ---------------------------------------------------------------------------
// Kernel 2: per-(aux n, batch b) slice. Aux peaks on the fly, ANDed with the
// L2-resident strain bitmask. inter+c2 packed in one u32 (fields <= 51200 <
// 2^16); c1 recomputed for free by popcounting mask words (each of the 1600
// words of batch b is owned by exactly one (tid&7)==0 thread per iteration).
// 2048 blocks x 256 threads, float4/thread/iter, 50 iters.
// ---------------------------------------------------------------------------
__global__ __launch_bounds__(256)
void aux_iou_kernel(const float* __restrict__ aux, float* __restrict__ out) {
    const int blk = blockIdx.x;          // 0..2047
    const int n   = blk >> 6;            // aux channel
    const int b   = blk & 63;            // batch
    const float* __restrict__ p = aux + (size_t)n * S_TOT;

    const int lane  = threadIdx.x & 31;
    const unsigned shift = (threadIdx.x & 7) * 4;   // loop-invariant bit offset
    const bool word_owner = (shift == 0);

    unsigned packed = 0;                 // bits[0:16)=inter, bits[16:32)=c2
    unsigned c1acc  = 0;

    int j = b * FT + threadIdx.x * 4;    // b*FT is 32-aligned -> shift formula holds
    int w = j >> 5;                      // mask word index, +32 per iter

    #pragma unroll 5
    for (int it = 0; it < FT / (256 * 4); ++it, j += 1024, w += 32) {   // 50 iters
        const float4 v = *reinterpret_cast<const float4*>(p + j);

        float left = __shfl_up_sync(FULL, v.w, 1);
        if (lane == 0)  left  = (j > 0) ? p[j - 1] : BIG_F;
        float right = __shfl_down_sync(FULL, v.x, 1);
        if (lane == 31) right = (j + 4 < S_TOT) ? p[j + 4] : BIG_F;

        const unsigned pk0 = (v.x >= THRESH) & (v.x > left) & (v.x > v.y);
        const unsigned pk1 = (v.y >= THRESH) & (v.y > v.x)  & (v.y > v.z);
        const unsigned pk2 = (v.z >= THRESH) & (v.z > v.y)  & (v.z > v.w);
        const unsigned pk3 = (v.w >= THRESH) & (v.w > v.z)  & (v.w > right);
        const unsigned nib = pk0 | (pk1 << 1) | (pk2 << 2) | (pk3 << 3);

        const unsigned mw  = g_mask[w];
        const unsigned mb4 = (mw >> shift) & 0xFu;

        packed += __popc(nib & mb4) | (__popc(nib) << 16);
        if (word_owner) c1acc += __popc(mw);
    }

    // block reduce (both accumulators; fields can't overflow 16 bits)
    __shared__ unsigned spk[8], sc1[8];
    #pragma unroll
    for (int off = 16; off > 0; off >>= 1) {
        packed += __shfl_down_sync(FULL, packed, off);
        c1acc  += __shfl_down_sync(FULL, c1acc,  off);
    }
    const int warp = threadIdx.x >> 5;
    if (lane == 0) { spk[warp] = packed; sc1[warp] = c1acc; }
    __syncthreads();
    if (threadIdx.x == 0) {
        unsigned tot = 0, tc1 = 0;
        #pragma unroll
        for (int k = 0; k < 8; ++k) { tot += spk[k]; tc1 += sc1[k]; }
        const int inter = (int)(tot & 0xffffu);
        const int c2    = (int)(tot >> 16);
        const int c1    = (int)tc1;

        const float fi  = (float)inter;
        const float fc1 = (float)c1;
        const float uni = fc1 + (float)c2 - fi;

        float jac, ratio;
        if (inter == 0 && uni == 0.0f) {          // empty & empty -> 1.0 (ref)
            jac = 1.0f; ratio = 1.0f;
        } else {
            jac   = fi / uni;                     // uni > 0 here
            ratio = (c1 > 0) ? (fi / fc1) : 0.0f; // 0/0 -> nan_to_num -> 0
        }
        const int o = n * B_DIM + b;
        out[o]      = jac;                        // iou, flat [N_aux*B]
        out[NB + o] = ratio;                      // corr, flat [N_aux*B]
    }
}

extern "C" void kernel_launch(void* const* d_in, const int* in_sizes, int n_in,
                              void* d_out, int out_size) {
    const float* strain = (const float*)d_in[0];   // [64, 80, 640] fp32
    const float* aux    = (const float*)d_in[1];   // [32, 64, 80, 640] fp32
    float* out = (float*)d_out;                    // [4096] = iou(2048) ++ corr(2048)

    strain_mask_kernel<<<S_TOT / (256 * 4), 256>>>(strain);
    aux_iou_kernel<<<NB, 256>>>(aux, out);
}

// round 6
// speedup vs baseline: 1.4474x; 1.0259x over previous
#include <cuda_runtime.h>
#include <stdint.h>

// Problem shape (fixed by the reference)
#define B_DIM   64
#define F_DIM   80
#define T_DIM   640
#define FT      (F_DIM * T_DIM)          // 51200
#define S_TOT   (B_DIM * FT)             // 3,276,800
#define N_AUX   32
#define NB      (N_AUX * B_DIM)          // 2048
#define MASK_WORDS (S_TOT / 32)          // 102400
#define THRESH  20.0f
#define BIG_F   3.0e38f                  // sentinel "no neighbor" => comparison false
#define FULL    0xffffffffu

// Scratch: strain peak bitmask (400 KB, L2-resident across the aux pass).
__device__ uint32_t g_mask[MASK_WORDS];

// ---------------------------------------------------------------------------
// Kernel 1: strain peak bitmask. One float4/thread, neighbors via shuffles,
// nibble->word packing via 3-step shfl_xor OR butterfly. Peak detection is on
// the WHOLE flattened [B,F,T] array (reference reshape(-1)); threshold > 0
// makes the reference's clip(.,0) redundant. ~4us.
// ---------------------------------------------------------------------------
__global__ __launch_bounds__(256)
void strain_mask_kernel(const float* __restrict__ x) {
    const int lane = threadIdx.x & 31;
    const int j = (blockIdx.x * 256 + threadIdx.x) * 4;

    const float4 v = *reinterpret_cast<const float4*>(x + j);

    float left = __shfl_up_sync(FULL, v.w, 1);
    if (lane == 0)  left  = (j > 0) ? x[j - 1] : BIG_F;
    float right = __shfl_down_sync(FULL, v.x, 1);
    if (lane == 31) right = (j + 4 < S_TOT) ? x[j + 4] : BIG_F;

    const unsigned pk0 = (v.x >= THRESH) & (v.x > left) & (v.x > v.y);
    const unsigned pk1 = (v.y >= THRESH) & (v.y > v.x)  & (v.y > v.z);
    const unsigned pk2 = (v.z >= THRESH) & (v.z > v.y)  & (v.z > v.w);
    const unsigned pk3 = (v.w >= THRESH) & (v.w > v.z)  & (v.w > right);

    unsigned val = (pk0 | (pk1 << 1) | (pk2 << 2) | (pk3 << 3)) << ((lane & 7) * 4);
    val |= __shfl_xor_sync(FULL, val, 1);
    val |= __shfl_xor_sync(FULL, val, 2);
    val |= __shfl_xor_sync(FULL, val, 4);
    if ((lane & 7) == 0) g_mask[j >> 5] = val;
}

// ---------------------------------------------------------------------------
// Kernel 2: per-(aux n, batch b) slice. Each thread processes 8 consecutive
// elements (two float4s) per iteration: fixed per-iter cost (2 shuffles,
// edge fixups, mask load, loop/index math) amortized over 2x the bytes, and
// the a.w|c.x neighbor boundary is register-local. Mask byte per thread at
// shift=(lane&3)*8; c1 recomputed for free by popcounting mask words
// ((lane&3)==0 owners). 2048 blocks x 256 threads, 32B/thread/iter, 25 iters.
// ---------------------------------------------------------------------------
__global__ __launch_bounds__(256)
void aux_iou_kernel(const float* __restrict__ aux, float* __restrict__ out) {
    const int blk = blockIdx.x;          // 0..2047
    const int n   = blk >> 6;            // aux channel
    const int b   = blk & 63;            // batch
    const float* __restrict__ p = aux + (size_t)n * S_TOT;

    const int lane = threadIdx.x & 31;
    const unsigned shift = (lane & 3) * 8;     // byte offset within mask word
    const bool word_owner = (lane & 3) == 0;

    unsigned packed = 0;                 // bits[0:16)=inter, bits[16:32)=c2
    unsigned c1acc  = 0;

    int e  = b * FT + threadIdx.x * 8;   // first element of this thread's 8
    int wi = e >> 5;                     // mask word index (+64 per iter)

    #pragma unroll 5
    for (int it = 0; it < FT / 2048; ++it, e += 2048, wi += 64) {   // 25 iters
        const float4 a = *reinterpret_cast<const float4*>(p + e);
        const float4 c = *reinterpret_cast<const float4*>(p + e + 4);
        const unsigned mw = g_mask[wi];

        float left = __shfl_up_sync(FULL, c.w, 1);
        if (lane == 0)  left  = (e > 0) ? p[e - 1] : BIG_F;
        float right = __shfl_down_sync(FULL, a.x, 1);
        if (lane == 31) right = (e + 8 < S_TOT) ? p[e + 8] : BIG_F;

        const unsigned pk0 = (a.x >= THRESH) & (a.x > left) & (a.x > a.y);
        const unsigned pk1 = (a.y >= THRESH) & (a.y > a.x)  & (a.y > a.z);
        const unsigned pk2 = (a.z >= THRESH) & (a.z > a.y)  & (a.z > a.w);
        const unsigned pk3 = (a.w >= THRESH) & (a.w > a.z)  & (a.w > c.x);
        const unsigned pk4 = (c.x >= THRESH) & (c.x > a.w)  & (c.x > c.y);
        const unsigned pk5 = (c.y >= THRESH) & (c.y > c.x)  & (c.y > c.z);
        const unsigned pk6 = (c.z >= THRESH) & (c.z > c.y)  & (c.z > c.w);
        const unsigned pk7 = (c.w >= THRESH) & (c.w > c.z)  & (c.w > right);

        const unsigned nib = pk0 | (pk1 << 1) | (pk2 << 2) | (pk3 << 3)
                           | (pk4 << 4) | (pk5 << 5) | (pk6 << 6) | (pk7 << 7);
        const unsigned mb8 = (mw >> shift) & 0xFFu;

        packed += __popc(nib & mb8) | (__popc(nib) << 16);
        if (word_owner) c1acc += __popc(mw);
    }

    // block reduce (fields can't overflow 16 bits: max peaks per slice < 25601)
    __shared__ unsigned spk[8], sc1[8];
    #pragma unroll
    for (int off = 16; off > 0; off >>= 1) {
        packed += __shfl_down_sync(FULL, packed, off);
        c1acc  += __shfl_down_sync(FULL, c1acc,  off);
    }
    const int warp = threadIdx.x >> 5;
    if (lane == 0) { spk[warp] = packed; sc1[warp] = c1acc; }
    __syncthreads();
    if (threadIdx.x == 0) {
        unsigned tot = 0, tc1 = 0;
        #pragma unroll
        for (int k = 0; k < 8; ++k) { tot += spk[k]; tc1 += sc1[k]; }
        const int inter = (int)(tot & 0xffffu);
        const int c2    = (int)(tot >> 16);
        const int c1    = (int)tc1;

        const float fi  = (float)inter;
        const float fc1 = (float)c1;
        const float uni = fc1 + (float)c2 - fi;

        float jac, ratio;
        if (inter == 0 && uni == 0.0f) {          // empty & empty -> 1.0 (ref)
            jac = 1.0f; ratio = 1.0f;
        } else {
            jac   = fi / uni;                     // uni > 0 here
            ratio = (c1 > 0) ? (fi / fc1) : 0.0f; // 0/0 -> nan_to_num -> 0
        }
        const int o = n * B_DIM + b;
        out[o]      = jac;                        // iou, flat [N_aux*B]
        out[NB + o] = ratio;                      // corr, flat [N_aux*B]
    }
}

extern "C" void kernel_launch(void* const* d_in, const int* in_sizes, int n_in,
                              void* d_out, int out_size) {
    const float* strain = (const float*)d_in[0];   // [64, 80, 640] fp32
    const float* aux    = (const float*)d_in[1];   // [32, 64, 80, 640] fp32
    float* out = (float*)d_out;                    // [4096] = iou(2048) ++ corr(2048)

    strain_mask_kernel<<<S_TOT / (256 * 4), 256>>>(strain);
    aux_iou_kernel<<<NB, 256>>>(aux, out);
}

// round 7
// speedup vs baseline: 1.5062x; 1.0407x over previous
#include <cuda_runtime.h>
#include <stdint.h>

// Problem shape (fixed by the reference)
#define B_DIM   64
#define F_DIM   80
#define T_DIM   640
#define FT      (F_DIM * T_DIM)          // 51200
#define S_TOT   (B_DIM * FT)             // 3,276,800
#define N_AUX   32
#define NB      (N_AUX * B_DIM)          // 2048
#define MASK_WORDS (S_TOT / 32)          // 102400
#define THRESH  20.0f
#define BIG_F   3.0e38f                  // sentinel "no neighbor" => comparison false
#define FULL    0xffffffffu

// Scratch: strain peak bitmask (400 KB, L2-resident across the aux pass).
__device__ uint32_t g_mask[MASK_WORDS];

// ---------------------------------------------------------------------------
// Kernel 1: strain peak bitmask. One float4/thread, neighbors via shuffles,
// nibble->word packing via 3-step shfl_xor OR butterfly. Peak detection is on
// the WHOLE flattened [B,F,T] array (reference reshape(-1)); threshold > 0
// makes the reference's clip(.,0) redundant. ~4us.
// ---------------------------------------------------------------------------
__global__ __launch_bounds__(256)
void strain_mask_kernel(const float* __restrict__ x) {
    const int lane = threadIdx.x & 31;
    const int j = (blockIdx.x * 256 + threadIdx.x) * 4;

    const float4 v = *reinterpret_cast<const float4*>(x + j);

    float left = __shfl_up_sync(FULL, v.w, 1);
    if (lane == 0)  left  = (j > 0) ? x[j - 1] : BIG_F;
    float right = __shfl_down_sync(FULL, v.x, 1);
    if (lane == 31) right = (j + 4 < S_TOT) ? x[j + 4] : BIG_F;

    const unsigned pk0 = (v.x >= THRESH) & (v.x > left) & (v.x > v.y);
    const unsigned pk1 = (v.y >= THRESH) & (v.y > v.x)  & (v.y > v.z);
    const unsigned pk2 = (v.z >= THRESH) & (v.z > v.y)  & (v.z > v.w);
    const unsigned pk3 = (v.w >= THRESH) & (v.w > v.z)  & (v.w > right);

    unsigned val = (pk0 | (pk1 << 1) | (pk2 << 2) | (pk3 << 3)) << ((lane & 7) * 4);
    val |= __shfl_xor_sync(FULL, val, 1);
    val |= __shfl_xor_sync(FULL, val, 2);
    val |= __shfl_xor_sync(FULL, val, 4);
    if ((lane & 7) == 0) g_mask[j >> 5] = val;
}

// ---------------------------------------------------------------------------
// Kernel 2: per-(aux n, batch b) slice, 8 consecutive elements/thread/iter.
// R7 changes: __launch_bounds__(256,8) caps regs at 32 -> 8 blocks/SM (full
// occupancy; more independent load streams to cover DRAM latency), unroll 2
// to fit the cap without spills, and __ldcs streaming loads so the 419MB
// one-pass aux stream doesn't evict the L2-resident strain mask.
// ---------------------------------------------------------------------------
__global__ __launch_bounds__(256, 8)
void aux_iou_kernel(const float* __restrict__ aux, float* __restrict__ out) {
    const int blk = blockIdx.x;          // 0..2047
    const int n   = blk >> 6;            // aux channel
    const int b   = blk & 63;            // batch
    const float* __restrict__ p = aux + (size_t)n * S_TOT;

    const int lane = threadIdx.x & 31;
    const unsigned shift = (lane & 3) * 8;     // byte offset within mask word
    const bool word_owner = (lane & 3) == 0;

    unsigned packed = 0;                 // bits[0:16)=inter, bits[16:32)=c2
    unsigned c1acc  = 0;

    int e  = b * FT + threadIdx.x * 8;   // first element of this thread's 8
    int wi = e >> 5;                     // mask word index (+64 per iter)

    #pragma unroll 2
    for (int it = 0; it < FT / 2048; ++it, e += 2048, wi += 64) {   // 25 iters
        const float4 a = __ldcs(reinterpret_cast<const float4*>(p + e));
        const float4 c = __ldcs(reinterpret_cast<const float4*>(p + e + 4));
        const unsigned mw = g_mask[wi];

        float left = __shfl_up_sync(FULL, c.w, 1);
        if (lane == 0)  left  = (e > 0) ? __ldcs(p + e - 1) : BIG_F;
        float right = __shfl_down_sync(FULL, a.x, 1);
        if (lane == 31) right = (e + 8 < S_TOT) ? __ldcs(p + e + 8) : BIG_F;

        const unsigned pk0 = (a.x >= THRESH) & (a.x > left) & (a.x > a.y);
        const unsigned pk1 = (a.y >= THRESH) & (a.y > a.x)  & (a.y > a.z);
        const unsigned pk2 = (a.z >= THRESH) & (a.z > a.y)  & (a.z > a.w);
        const unsigned pk3 = (a.w >= THRESH) & (a.w > a.z)  & (a.w > c.x);
        const unsigned pk4 = (c.x >= THRESH) & (c.x > a.w)  & (c.x > c.y);
        const unsigned pk5 = (c.y >= THRESH) & (c.y > c.x)  & (c.y > c.z);
        const unsigned pk6 = (c.z >= THRESH) & (c.z > c.y)  & (c.z > c.w);
        const unsigned pk7 = (c.w >= THRESH) & (c.w > c.z)  & (c.w > right);

        const unsigned nib = pk0 | (pk1 << 1) | (pk2 << 2) | (pk3 << 3)
                           | (pk4 << 4) | (pk5 << 5) | (pk6 << 6) | (pk7 << 7);
        const unsigned mb8 = (mw >> shift) & 0xFFu;

        packed += __popc(nib & mb8) | (__popc(nib) << 16);
        if (word_owner) c1acc += __popc(mw);
    }

    // block reduce (fields can't overflow 16 bits: max peaks per slice < 25601)
    __shared__ unsigned spk[8], sc1[8];
    #pragma unroll
    for (int off = 16; off > 0; off >>= 1) {
        packed += __shfl_down_sync(FULL, packed, off);
        c1acc  += __shfl_down_sync(FULL, c1acc,  off);
    }
    const int warp = threadIdx.x >> 5;
    if (lane == 0) { spk[warp] = packed; sc1[warp] = c1acc; }
    __syncthreads();
    if (threadIdx.x == 0) {
        unsigned tot = 0, tc1 = 0;
        #pragma unroll
        for (int k = 0; k < 8; ++k) { tot += spk[k]; tc1 += sc1[k]; }
        const int inter = (int)(tot & 0xffffu);
        const int c2    = (int)(tot >> 16);
        const int c1    = (int)tc1;

        const float fi  = (float)inter;
        const float fc1 = (float)c1;
        const float uni = fc1 + (float)c2 - fi;

        float jac, ratio;
        if (inter == 0 && uni == 0.0f) {          // empty & empty -> 1.0 (ref)
            jac = 1.0f; ratio = 1.0f;
        } else {
            jac   = fi / uni;                     // uni > 0 here
            ratio = (c1 > 0) ? (fi / fc1) : 0.0f; // 0/0 -> nan_to_num -> 0
        }
        const int o = n * B_DIM + b;
        out[o]      = jac;                        // iou, flat [N_aux*B]
        out[NB + o] = ratio;                      // corr, flat [N_aux*B]
    }
}

extern "C" void kernel_launch(void* const* d_in, const int* in_sizes, int n_in,
                              void* d_out, int out_size) {
    const float* strain = (const float*)d_in[0];   // [64, 80, 640] fp32
    const float* aux    = (const float*)d_in[1];   // [32, 64, 80, 640] fp32
    float* out = (float*)d_out;                    // [4096] = iou(2048) ++ corr(2048)

    strain_mask_kernel<<<S_TOT / (256 * 4), 256>>>(strain);
    aux_iou_kernel<<<NB, 256>>>(aux, out);
}

// round 8
// speedup vs baseline: 1.5278x; 1.0143x over previous
#include <cuda_runtime.h>
#include <stdint.h>

// Problem shape (fixed by the reference)
#define B_DIM   64
#define F_DIM   80
#define T_DIM   640
#define FT      (F_DIM * T_DIM)          // 51200
#define S_TOT   (B_DIM * FT)             // 3,276,800
#define N_AUX   32
#define NB      (N_AUX * B_DIM)          // 2048
#define MASK_WORDS (S_TOT / 32)          // 102400
#define THRESH  20.0f
#define BIG_F   3.0e38f                  // sentinel "no neighbor" => comparison false
#define FULL    0xffffffffu

// Scratch: strain peak bitmask (400 KB, L2-resident across the aux pass).
__device__ uint32_t g_mask[MASK_WORDS];

// ---------------------------------------------------------------------------
// Kernel 1: strain peak bitmask. One float4/thread, neighbors via shuffles,
// nibble->word packing via 3-step shfl_xor OR butterfly. Peak detection is on
// the WHOLE flattened [B,F,T] array (reference reshape(-1)); threshold > 0
// makes the reference's clip(.,0) redundant. ~2us.
// ---------------------------------------------------------------------------
__global__ __launch_bounds__(256)
void strain_mask_kernel(const float* __restrict__ x) {
    const int lane = threadIdx.x & 31;
    const int j = (blockIdx.x * 256 + threadIdx.x) * 4;

    const float4 v = *reinterpret_cast<const float4*>(x + j);

    float left = __shfl_up_sync(FULL, v.w, 1);
    if (lane == 0)  left  = (j > 0) ? x[j - 1] : BIG_F;
    float right = __shfl_down_sync(FULL, v.x, 1);
    if (lane == 31) right = (j + 4 < S_TOT) ? x[j + 4] : BIG_F;

    const unsigned pk0 = (v.x >= THRESH) & (v.x > left) & (v.x > v.y);
    const unsigned pk1 = (v.y >= THRESH) & (v.y > v.x)  & (v.y > v.z);
    const unsigned pk2 = (v.z >= THRESH) & (v.z > v.y)  & (v.z > v.w);
    const unsigned pk3 = (v.w >= THRESH) & (v.w > v.z)  & (v.w > right);

    unsigned val = (pk0 | (pk1 << 1) | (pk2 << 2) | (pk3 << 3)) << ((lane & 7) * 4);
    val |= __shfl_xor_sync(FULL, val, 1);
    val |= __shfl_xor_sync(FULL, val, 2);
    val |= __shfl_xor_sync(FULL, val, 4);
    if ((lane & 7) == 0) g_mask[j >> 5] = val;
}

// ---------------------------------------------------------------------------
// Kernel 2: per-(aux n, batch b) slice, 8 consecutive elements/thread/iter.
// R8: 128-thread blocks with __launch_bounds__(128,16) -> 2368 resident block
// slots >= 2048 blocks -> the ENTIRE grid is one wave (R7 profile showed 1.73
// waves; the 864-block second wave idled ~27% of the chip). Per-SM warp count
// unchanged (64); per-block work identical -> near-perfect balance.
// __ldcs streaming keeps the 419MB one-pass aux stream from evicting the
// L2-resident strain mask. c1 popcounted for free by (lane&3)==0 owners.
// ---------------------------------------------------------------------------
__global__ __launch_bounds__(128, 16)
void aux_iou_kernel(const float* __restrict__ aux, float* __restrict__ out) {
    const int blk = blockIdx.x;          // 0..2047
    const int n   = blk >> 6;            // aux channel
    const int b   = blk & 63;            // batch
    const float* __restrict__ p = aux + (size_t)n * S_TOT;

    const int lane = threadIdx.x & 31;
    const unsigned shift = (lane & 3) * 8;     // byte offset within mask word
    const bool word_owner = (lane & 3) == 0;

    unsigned packed = 0;                 // bits[0:16)=inter, bits[16:32)=c2
    unsigned c1acc  = 0;

    int e  = b * FT + threadIdx.x * 8;   // first element of this thread's 8
    int wi = e >> 5;                     // mask word index (+32 per iter)

    #pragma unroll 2
    for (int it = 0; it < FT / 1024; ++it, e += 1024, wi += 32) {   // 50 iters
        const float4 a = __ldcs(reinterpret_cast<const float4*>(p + e));
        const float4 c = __ldcs(reinterpret_cast<const float4*>(p + e + 4));
        const unsigned mw = g_mask[wi];

        float left = __shfl_up_sync(FULL, c.w, 1);
        if (lane == 0)  left  = (e > 0) ? __ldcs(p + e - 1) : BIG_F;
        float right = __shfl_down_sync(FULL, a.x, 1);
        if (lane == 31) right = (e + 8 < S_TOT) ? __ldcs(p + e + 8) : BIG_F;

        const unsigned pk0 = (a.x >= THRESH) & (a.x > left) & (a.x > a.y);
        const unsigned pk1 = (a.y >= THRESH) & (a.y > a.x)  & (a.y > a.z);
        const unsigned pk2 = (a.z >= THRESH) & (a.z > a.y)  & (a.z > a.w);
        const unsigned pk3 = (a.w >= THRESH) & (a.w > a.z)  & (a.w > c.x);
        const unsigned pk4 = (c.x >= THRESH) & (c.x > a.w)  & (c.x > c.y);
        const unsigned pk5 = (c.y >= THRESH) & (c.y > c.x)  & (c.y > c.z);
        const unsigned pk6 = (c.z >= THRESH) & (c.z > c.y)  & (c.z > c.w);
        const unsigned pk7 = (c.w >= THRESH) & (c.w > c.z)  & (c.w > right);

        const unsigned nib = pk0 | (pk1 << 1) | (pk2 << 2) | (pk3 << 3)
                           | (pk4 << 4) | (pk5 << 5) | (pk6 << 6) | (pk7 << 7);
        const unsigned mb8 = (mw >> shift) & 0xFFu;

        packed += __popc(nib & mb8) | (__popc(nib) << 16);
        if (word_owner) c1acc += __popc(mw);
    }

    // block reduce (fields can't overflow 16 bits: max peaks per slice < 25601)
    __shared__ unsigned spk[4], sc1[4];
    #pragma unroll
    for (int off = 16; off > 0; off >>= 1) {
        packed += __shfl_down_sync(FULL, packed, off);
        c1acc  += __shfl_down_sync(FULL, c1acc,  off);
    }
    const int warp = threadIdx.x >> 5;
    if (lane == 0) { spk[warp] = packed; sc1[warp] = c1acc; }
    __syncthreads();
    if (threadIdx.x == 0) {
        unsigned tot = 0, tc1 = 0;
        #pragma unroll
        for (int k = 0; k < 4; ++k) { tot += spk[k]; tc1 += sc1[k]; }
        const int inter = (int)(tot & 0xffffu);
        const int c2    = (int)(tot >> 16);
        const int c1    = (int)tc1;

        const float fi  = (float)inter;
        const float fc1 = (float)c1;
        const float uni = fc1 + (float)c2 - fi;

        float jac, ratio;
        if (inter == 0 && uni == 0.0f) {          // empty & empty -> 1.0 (ref)
            jac = 1.0f; ratio = 1.0f;
        } else {
            jac   = fi / uni;                     // uni > 0 here
            ratio = (c1 > 0) ? (fi / fc1) : 0.0f; // 0/0 -> nan_to_num -> 0
        }
        const int o = n * B_DIM + b;
        out[o]      = jac;                        // iou, flat [N_aux*B]
        out[NB + o] = ratio;                      // corr, flat [N_aux*B]
    }
}

extern "C" void kernel_launch(void* const* d_in, const int* in_sizes, int n_in,
                              void* d_out, int out_size) {
    const float* strain = (const float*)d_in[0];   // [64, 80, 640] fp32
    const float* aux    = (const float*)d_in[1];   // [32, 64, 80, 640] fp32
    float* out = (float*)d_out;                    // [4096] = iou(2048) ++ corr(2048)

    strain_mask_kernel<<<S_TOT / (256 * 4), 256>>>(strain);
    aux_iou_kernel<<<NB, 128>>>(aux, out);
}